// round 7
// baseline (speedup 1.0000x reference)
#include <cuda_runtime.h>
#include <cuda_bf16.h>
#include <cstdint>

// ============================ problem dims ============================
static constexpr int B_ = 4, H_ = 8, N_ = 2048, D_ = 64;
static constexpr int BH = B_ * H_;   // 32
static constexpr int BM = 128;       // query rows per CTA (32 per warp)
static constexpr int BN = 64;        // keys per tile
static constexpr int MT = N_ / BM;   // 16
static constexpr int NT = N_ / BN;   // 32

// ==================== pre-converted gmem scratch ======================
// SW128-preswizzled bf16 tile images: main kernel does pure 16B cp.async.
// Q image per (bh, mt): 128 rows x 128B = 16KB. K/V per (bh, nt): 64 x 128B = 8KB.
__device__ __align__(128) uint8_t g_qhi[(size_t)BH * MT * 16384];
__device__ __align__(128) uint8_t g_qlo[(size_t)BH * MT * 16384];
__device__ __align__(128) uint8_t g_khi[(size_t)BH * NT * 8192];
__device__ __align__(128) uint8_t g_klo[(size_t)BH * NT * 8192];
__device__ __align__(128) uint8_t g_vhi[(size_t)BH * NT * 8192];
__device__ __align__(128) uint8_t g_vlo[(size_t)BH * NT * 8192];
__device__ float g_kk[(size_t)BH * N_];   // holds -0.125 * log2(e) * ||k||^2

// ============================ helpers =============================
__device__ __forceinline__ uint32_t smem_u32(const void* p) {
    uint32_t a;
    asm("{ .reg .u64 t; cvta.to.shared.u64 t, %1; cvt.u32.u64 %0, t; }" : "=r"(a) : "l"(p));
    return a;
}
__device__ __forceinline__ void cpa16(uint32_t s, const void* g) {
    asm volatile("cp.async.cg.shared.global [%0], [%1], 16;" :: "r"(s), "l"(g));
}
__device__ __forceinline__ void cpa_commit() { asm volatile("cp.async.commit_group;" ::: "memory"); }
__device__ __forceinline__ void cpa_wait0()  { asm volatile("cp.async.wait_group 0;" ::: "memory"); }

__device__ __forceinline__ void ldmx4(uint32_t* r, uint32_t a) {
    asm volatile("ldmatrix.sync.aligned.m8n8.x4.shared.b16 {%0,%1,%2,%3}, [%4];"
                 : "=r"(r[0]), "=r"(r[1]), "=r"(r[2]), "=r"(r[3]) : "r"(a));
}
__device__ __forceinline__ void ldmx4t(uint32_t* r, uint32_t a) {
    asm volatile("ldmatrix.sync.aligned.m8n8.x4.trans.shared.b16 {%0,%1,%2,%3}, [%4];"
                 : "=r"(r[0]), "=r"(r[1]), "=r"(r[2]), "=r"(r[3]) : "r"(a));
}
// D += A * B  (m16n8k16, bf16 in, fp32 accum)
__device__ __forceinline__ void mma16816(float* c, const uint32_t* a, uint32_t b0, uint32_t b1) {
    asm volatile("mma.sync.aligned.m16n8k16.row.col.f32.bf16.bf16.f32 "
                 "{%0,%1,%2,%3}, {%4,%5,%6,%7}, {%8,%9}, {%0,%1,%2,%3};"
                 : "+f"(c[0]), "+f"(c[1]), "+f"(c[2]), "+f"(c[3])
                 : "r"(a[0]), "r"(a[1]), "r"(a[2]), "r"(a[3]), "r"(b0), "r"(b1));
}
__device__ __forceinline__ uint32_t pkbf2(float up, float low) {
    uint32_t d;
    asm("cvt.rn.bf16x2.f32 %0, %1, %2;" : "=r"(d) : "f"(up), "f"(low));
    return d;
}
__device__ __forceinline__ float lo_f32(uint32_t p) { return __uint_as_float(p << 16); }
__device__ __forceinline__ float hi_f32(uint32_t p) { return __uint_as_float(p & 0xffff0000u); }
__device__ __forceinline__ float ex2f(float x) {
    float y;
    asm("ex2.approx.f32 %0, %1;" : "=f"(y) : "f"(x));
    return y;
}
static constexpr float LOG2E   = 1.4426950408889634f;
static constexpr float SCALE_S = 0.25f * LOG2E;

// ====================== pre-pass: fp32 -> SW128 bf16 hi/lo images ======================
__global__ void prep_kernel(const float* __restrict__ q, const float* __restrict__ k,
                            const float* __restrict__ v) {
    int idx  = blockIdx.x * 256 + threadIdx.x;   // 0 .. BH*N*8-1
    int rown = idx >> 3;
    int c    = idx & 7;
    int d0   = c * 8;
    int bh = rown >> 11, n = rown & 2047;

    auto split8 = [&](const float* src, uint8_t* dh, uint8_t* dl, uint32_t rowoff, float* ss) {
        float xs[8];
        *(float4*)(xs)     = *(const float4*)(src);
        *(float4*)(xs + 4) = *(const float4*)(src + 4);
        uint32_t hp[4], lp[4];
        #pragma unroll
        for (int j = 0; j < 4; j++) {
            float x0 = xs[2 * j], x1 = xs[2 * j + 1];
            if (ss) *ss += x0 * x0 + x1 * x1;
            uint32_t hpair = pkbf2(x1, x0);
            hp[j] = hpair;
            lp[j] = pkbf2(x1 - hi_f32(hpair), x0 - lo_f32(hpair));
        }
        uint32_t x = rowoff + (uint32_t)d0 * 2;
        uint32_t off = x ^ ((x >> 3) & 0x70);
        *(uint4*)(dh + off) = make_uint4(hp[0], hp[1], hp[2], hp[3]);
        *(uint4*)(dl + off) = make_uint4(lp[0], lp[1], lp[2], lp[3]);
    };

    {   // Q (128-row tiles)
        int qmt = n >> 7, r = n & 127;
        split8(q + (size_t)rown * 64 + d0,
               g_qhi + (((size_t)(bh * MT + qmt)) << 14),
               g_qlo + (((size_t)(bh * MT + qmt)) << 14),
               (uint32_t)r * 128, nullptr);
    }
    {   // K + kk
        int nt = n >> 6, r = n & 63;
        float ss = 0.f;
        split8(k + (size_t)rown * 64 + d0,
               g_khi + (((size_t)(bh * NT + nt)) << 13),
               g_klo + (((size_t)(bh * NT + nt)) << 13),
               (uint32_t)r * 128, &ss);
        ss += __shfl_xor_sync(0xffffffffu, ss, 1);
        ss += __shfl_xor_sync(0xffffffffu, ss, 2);
        ss += __shfl_xor_sync(0xffffffffu, ss, 4);
        if (c == 0) g_kk[rown] = -0.125f * LOG2E * ss;
    }
    {   // V
        int nt = n >> 6, r = n & 63;
        split8(v + (size_t)rown * 64 + d0,
               g_vhi + (((size_t)(bh * NT + nt)) << 13),
               g_vlo + (((size_t)(bh * NT + nt)) << 13),
               (uint32_t)r * 128, nullptr);
    }
}

// =========================== main kernel ===========================
// smem: KV ring of 2 x 32KB at [0,64K). Q image (16KB hi + 16KB lo) staged
// at [32K,64K) = buf1's footprint during prologue, consumed to registers,
// then buf1 reuses that space.
static constexpr uint32_t S_KV  = 0;
static constexpr uint32_t S_QH  = 32768;
static constexpr uint32_t S_QL  = 49152;
static constexpr uint32_t S_KK  = 65536;    // 2 x 256B
static constexpr uint32_t SMEM_BYTES = 65536 + 512;

__global__ __launch_bounds__(128, 2)
void attn_main(float* __restrict__ out) {
    extern __shared__ __align__(1024) uint8_t smem[];
    const uint32_t sb = smem_u32(smem);
    const int tid = threadIdx.x, wid = tid >> 5, lane = tid & 31;
    const int mt = blockIdx.x, bh = blockIdx.y;
    const int b = bh >> 3, h = bh & 7;
    const int mrank = lane >> 3;
    const int l7 = lane & 7;

    // ---- prologue: Q images (staged) + KV tile 0 ----
    {
        const uint8_t* qh = g_qhi + (((size_t)(bh * MT + mt)) << 14);
        const uint8_t* ql = g_qlo + (((size_t)(bh * MT + mt)) << 14);
        #pragma unroll
        for (int i = 0; i < 8; i++) {
            int o = (tid + 128 * i) * 16;
            cpa16(sb + S_QH + o, qh + o);
            cpa16(sb + S_QL + o, ql + o);
        }
        const size_t t0 = ((size_t)(bh * NT)) << 13;
        #pragma unroll
        for (int i = 0; i < 4; i++) {
            int o = (tid + 128 * i) * 16;
            cpa16(sb + S_KV +          o, g_khi + t0 + o);
            cpa16(sb + S_KV +  8192 + o, g_klo + t0 + o);
            cpa16(sb + S_KV + 16384 + o, g_vhi + t0 + o);
            cpa16(sb + S_KV + 24576 + o, g_vlo + t0 + o);
        }
        if (tid < 16) cpa16(sb + S_KK + tid * 16, g_kk + (size_t)bh * N_ + tid * 4);
        cpa_commit();
        cpa_wait0();
    }
    __syncthreads();

    // ---- Q A-fragments: 2 m16 blocks per warp (rows wid*32 .. wid*32+31) ----
    uint32_t Qh[2][4][4], Ql[2][4][4];
    #pragma unroll
    for (int mb = 0; mb < 2; mb++) {
        int qrow = wid * 32 + mb * 16 + ((mrank & 1) << 3) + l7;
        uint32_t rbase = (uint32_t)qrow * 128;
        uint32_t rx = (uint32_t)((qrow & 7) << 4);
        #pragma unroll
        for (int ks = 0; ks < 4; ks++) {
            uint32_t colb = (uint32_t)(ks * 32 + ((mrank >> 1) << 4));
            uint32_t a = sb + S_QH + rbase + (colb ^ rx);
            ldmx4(Qh[mb][ks], a);
            ldmx4(Ql[mb][ks], a + 16384);
        }
    }
    // all warps must finish reading Q before buf1 (same bytes) is overwritten
    __syncthreads();

    float O[2][8][4];
    #pragma unroll
    for (int mb = 0; mb < 2; mb++)
        #pragma unroll
        for (int i = 0; i < 8; i++)
            #pragma unroll
            for (int j = 0; j < 4; j++) O[mb][i][j] = 0.f;
    float Lp[2][2] = {{0.f, 0.f}, {0.f, 0.f}};

    const int krow16 = ((mrank >> 1) << 3) + l7;
    const int vrow16 = ((mrank & 1) << 3) + l7;
    const uint32_t kcol = (uint32_t)((mrank & 1) << 4);
    const uint32_t vcol = (uint32_t)((mrank >> 1) << 4);

    #pragma unroll 1
    for (int kt = 0; kt < NT; kt++) {
        const uint32_t cb = sb + S_KV + (uint32_t)(kt & 1) * 32768;

        // prefetch tile kt+1 into the other buffer
        if (kt + 1 < NT) {
            const size_t toff = ((size_t)(bh * NT + kt + 1)) << 13;
            const uint32_t dst = sb + S_KV + (uint32_t)((kt + 1) & 1) * 32768;
            #pragma unroll
            for (int i = 0; i < 4; i++) {
                int o = (tid + 128 * i) * 16;
                cpa16(dst +          o, g_khi + toff + o);
                cpa16(dst +  8192 + o, g_klo + toff + o);
                cpa16(dst + 16384 + o, g_vhi + toff + o);
                cpa16(dst + 24576 + o, g_vlo + toff + o);
            }
            if (tid < 16) cpa16(sb + S_KK + ((kt + 1) & 1) * 256 + tid * 16,
                                g_kk + (size_t)bh * N_ + (size_t)(kt + 1) * 64 + tid * 4);
            cpa_commit();
        }

        const float* kkp = (const float*)(smem + S_KK + (kt & 1) * 256);

        // ---- per 16-key block: S -> softmax -> PV (S and P transient) ----
        #pragma unroll
        for (int np = 0; np < 4; np++) {
            float S[2][2][4];
            #pragma unroll
            for (int mb = 0; mb < 2; mb++)
                #pragma unroll
                for (int nb = 0; nb < 2; nb++)
                    #pragma unroll
                    for (int j = 0; j < 4; j++) S[mb][nb][j] = 0.f;

            {   // S block: 48 MMAs, 8 LDSM
                const int row = np * 16 + krow16;
                const uint32_t rowa = cb + (uint32_t)row * 128;
                const uint32_t rx = (uint32_t)((row & 7) << 4);
                #pragma unroll
                for (int ks = 0; ks < 4; ks++) {
                    uint32_t a = rowa + (((uint32_t)(ks * 32) + kcol) ^ rx);
                    uint32_t KBh[4], KBl[4];
                    ldmx4(KBh, a);
                    ldmx4(KBl, a + 8192);
                    #pragma unroll
                    for (int mb = 0; mb < 2; mb++) {
                        mma16816(S[mb][0], Qh[mb][ks], KBh[0], KBh[1]);
                        mma16816(S[mb][1], Qh[mb][ks], KBh[2], KBh[3]);
                        mma16816(S[mb][0], Ql[mb][ks], KBh[0], KBh[1]);
                        mma16816(S[mb][1], Ql[mb][ks], KBh[2], KBh[3]);
                        mma16816(S[mb][0], Qh[mb][ks], KBl[0], KBl[1]);
                        mma16816(S[mb][1], Qh[mb][ks], KBl[2], KBl[3]);
                    }
                }
            }

            // softmax numerator -> transient P fragments
            uint32_t Ph[2][4], Pl[2][4];
            #pragma unroll
            for (int mb = 0; mb < 2; mb++) {
                #pragma unroll
                for (int t = 0; t < 2; t++) {
                    const int col = np * 16 + t * 8 + 2 * (lane & 3);
                    float k0 = kkp[col], k1 = kkp[col + 1];
                    float p0 = ex2f(fmaf(SCALE_S, S[mb][t][0], k0));
                    float p1 = ex2f(fmaf(SCALE_S, S[mb][t][1], k1));
                    float p2 = ex2f(fmaf(SCALE_S, S[mb][t][2], k0));
                    float p3 = ex2f(fmaf(SCALE_S, S[mb][t][3], k1));
                    Lp[mb][0] += p0 + p1;
                    Lp[mb][1] += p2 + p3;
                    uint32_t h01 = pkbf2(p1, p0);
                    uint32_t h23 = pkbf2(p3, p2);
                    Ph[mb][2 * t]     = h01;
                    Ph[mb][2 * t + 1] = h23;
                    Pl[mb][2 * t]     = pkbf2(p1 - hi_f32(h01), p0 - lo_f32(h01));
                    Pl[mb][2 * t + 1] = pkbf2(p3 - hi_f32(h23), p2 - lo_f32(h23));
                }
            }

            {   // PV block: 48 MMAs, 8 LDSM
                const int row = np * 16 + vrow16;
                const uint32_t rowa = cb + 16384 + (uint32_t)row * 128;
                const uint32_t rx = (uint32_t)((row & 7) << 4);
                #pragma unroll
                for (int dp = 0; dp < 4; dp++) {
                    uint32_t a = rowa + (((uint32_t)(dp * 32) + vcol) ^ rx);
                    uint32_t VBh[4], VBl[4];
                    ldmx4t(VBh, a);
                    ldmx4t(VBl, a + 8192);
                    #pragma unroll
                    for (int mb = 0; mb < 2; mb++) {
                        mma16816(O[mb][2 * dp],     Ph[mb], VBh[0], VBh[1]);
                        mma16816(O[mb][2 * dp + 1], Ph[mb], VBh[2], VBh[3]);
                        mma16816(O[mb][2 * dp],     Pl[mb], VBh[0], VBh[1]);
                        mma16816(O[mb][2 * dp + 1], Pl[mb], VBh[2], VBh[3]);
                        mma16816(O[mb][2 * dp],     Ph[mb], VBl[0], VBl[1]);
                        mma16816(O[mb][2 * dp + 1], Ph[mb], VBl[2], VBl[3]);
                    }
                }
            }
        }

        // tile kt+1 arrival + gate buffer reuse (single barrier per tile)
        if (kt + 1 < NT) {
            cpa_wait0();
            __syncthreads();
        }
    }

    // ---- epilogue: reduce row sums across quads, normalize, store ----
    #pragma unroll
    for (int mb = 0; mb < 2; mb++) {
        float L0 = Lp[mb][0], L1 = Lp[mb][1];
        L0 += __shfl_xor_sync(0xffffffffu, L0, 1);
        L0 += __shfl_xor_sync(0xffffffffu, L0, 2);
        L1 += __shfl_xor_sync(0xffffffffu, L1, 1);
        L1 += __shfl_xor_sync(0xffffffffu, L1, 2);
        float inv0 = 1.0f / L0;
        float inv1 = 1.0f / L1;

        const int r0 = mt * BM + wid * 32 + mb * 16 + (lane >> 2);
        const int dbase = 2 * (lane & 3);
        float* o0 = out + (((size_t)(b * N_ + r0) * H_ + h) << 6);
        float* o1 = out + (((size_t)(b * N_ + r0 + 8) * H_ + h) << 6);
        #pragma unroll
        for (int dt = 0; dt < 8; dt++) {
            int d = dt * 8 + dbase;
            float2 a0 = make_float2(O[mb][dt][0] * inv0, O[mb][dt][1] * inv0);
            float2 a1 = make_float2(O[mb][dt][2] * inv1, O[mb][dt][3] * inv1);
            *(float2*)(o0 + d) = a0;
            *(float2*)(o1 + d) = a1;
        }
    }
}

// ============================ launch ============================
extern "C" void kernel_launch(void* const* d_in, const int* in_sizes, int n_in,
                              void* d_out, int out_size) {
    (void)in_sizes; (void)n_in; (void)out_size;
    const float* q = (const float*)d_in[0];
    const float* k = (const float*)d_in[1];
    const float* v = (const float*)d_in[2];
    float* out = (float*)d_out;

    prep_kernel<<<BH * N_ * 8 / 256, 256>>>(q, k, v);

    cudaFuncSetAttribute(attn_main, cudaFuncAttributeMaxDynamicSharedMemorySize, SMEM_BYTES);
    dim3 grid(MT, BH);
    attn_main<<<grid, 128, SMEM_BYTES>>>(out);
}

// round 8
// speedup vs baseline: 1.0784x; 1.0784x over previous
#include <cuda_runtime.h>
#include <cuda_bf16.h>
#include <cstdint>

// ============================ problem dims ============================
static constexpr int B_ = 4, H_ = 8, N_ = 2048, D_ = 64;
static constexpr int BH = B_ * H_;   // 32
static constexpr int BM = 64;        // query rows per CTA
static constexpr int BN = 64;        // keys per tile
static constexpr int MT = N_ / BM;   // 32
static constexpr int NT = N_ / BN;   // 32
static constexpr int NSPLIT = 3;     // key-dimension splits (tiles 0-10, 11-21, 22-31)

// ==================== pre-converted gmem scratch ======================
__device__ __align__(128) uint8_t g_qhi[(size_t)BH * MT * 8192];
__device__ __align__(128) uint8_t g_qlo[(size_t)BH * MT * 8192];
__device__ __align__(128) uint8_t g_khi[(size_t)BH * NT * 8192];
__device__ __align__(128) uint8_t g_klo[(size_t)BH * NT * 8192];
__device__ __align__(128) uint8_t g_vhi[(size_t)BH * NT * 8192];
__device__ __align__(128) uint8_t g_vlo[(size_t)BH * NT * 8192];
__device__ float g_kk[(size_t)BH * N_];   // -0.125 * log2(e) * ||k||^2

// split-K partials
__device__ float g_opart[(size_t)NSPLIT * BH * N_ * D_];
__device__ float g_lpart[(size_t)NSPLIT * BH * N_];

// ============================ helpers =============================
__device__ __forceinline__ uint32_t smem_u32(const void* p) {
    uint32_t a;
    asm("{ .reg .u64 t; cvta.to.shared.u64 t, %1; cvt.u32.u64 %0, t; }" : "=r"(a) : "l"(p));
    return a;
}
__device__ __forceinline__ void cpa16(uint32_t s, const void* g) {
    asm volatile("cp.async.cg.shared.global [%0], [%1], 16;" :: "r"(s), "l"(g));
}
__device__ __forceinline__ void cpa_commit() { asm volatile("cp.async.commit_group;" ::: "memory"); }
__device__ __forceinline__ void cpa_wait0()  { asm volatile("cp.async.wait_group 0;" ::: "memory"); }

__device__ __forceinline__ void ldmx4(uint32_t* r, uint32_t a) {
    asm volatile("ldmatrix.sync.aligned.m8n8.x4.shared.b16 {%0,%1,%2,%3}, [%4];"
                 : "=r"(r[0]), "=r"(r[1]), "=r"(r[2]), "=r"(r[3]) : "r"(a));
}
__device__ __forceinline__ void ldmx4t(uint32_t* r, uint32_t a) {
    asm volatile("ldmatrix.sync.aligned.m8n8.x4.trans.shared.b16 {%0,%1,%2,%3}, [%4];"
                 : "=r"(r[0]), "=r"(r[1]), "=r"(r[2]), "=r"(r[3]) : "r"(a));
}
__device__ __forceinline__ void mma16816(float* c, const uint32_t* a, uint32_t b0, uint32_t b1) {
    asm volatile("mma.sync.aligned.m16n8k16.row.col.f32.bf16.bf16.f32 "
                 "{%0,%1,%2,%3}, {%4,%5,%6,%7}, {%8,%9}, {%0,%1,%2,%3};"
                 : "+f"(c[0]), "+f"(c[1]), "+f"(c[2]), "+f"(c[3])
                 : "r"(a[0]), "r"(a[1]), "r"(a[2]), "r"(a[3]), "r"(b0), "r"(b1));
}
__device__ __forceinline__ uint32_t pkbf2(float up, float low) {
    uint32_t d;
    asm("cvt.rn.bf16x2.f32 %0, %1, %2;" : "=r"(d) : "f"(up), "f"(low));
    return d;
}
__device__ __forceinline__ float lo_f32(uint32_t p) { return __uint_as_float(p << 16); }
__device__ __forceinline__ float hi_f32(uint32_t p) { return __uint_as_float(p & 0xffff0000u); }
__device__ __forceinline__ float ex2f(float x) {
    float y;
    asm("ex2.approx.f32 %0, %1;" : "=f"(y) : "f"(x));
    return y;
}
static constexpr float LOG2E   = 1.4426950408889634f;
static constexpr float SCALE_S = 0.25f * LOG2E;

// ====================== pre-pass: fp32 -> SW128 bf16 hi/lo images ======================
__global__ void prep_kernel(const float* __restrict__ q, const float* __restrict__ k,
                            const float* __restrict__ v) {
    int idx  = blockIdx.x * 256 + threadIdx.x;   // 0 .. BH*N*8-1
    int rown = idx >> 3;
    int c    = idx & 7;
    int d0   = c * 8;
    int bh = rown >> 11, n = rown & 2047;

    auto split8 = [&](const float* src, uint8_t* dh, uint8_t* dl, uint32_t rowoff, float* ss) {
        float xs[8];
        *(float4*)(xs)     = *(const float4*)(src);
        *(float4*)(xs + 4) = *(const float4*)(src + 4);
        uint32_t hp[4], lp[4];
        #pragma unroll
        for (int j = 0; j < 4; j++) {
            float x0 = xs[2 * j], x1 = xs[2 * j + 1];
            if (ss) *ss += x0 * x0 + x1 * x1;
            uint32_t hpair = pkbf2(x1, x0);
            hp[j] = hpair;
            lp[j] = pkbf2(x1 - hi_f32(hpair), x0 - lo_f32(hpair));
        }
        uint32_t x = rowoff + (uint32_t)d0 * 2;
        uint32_t off = x ^ ((x >> 3) & 0x70);
        *(uint4*)(dh + off) = make_uint4(hp[0], hp[1], hp[2], hp[3]);
        *(uint4*)(dl + off) = make_uint4(lp[0], lp[1], lp[2], lp[3]);
    };

    {   // Q
        int qmt = n >> 6, r = n & 63;
        split8(q + (size_t)rown * 64 + d0,
               g_qhi + (((size_t)(bh * MT + qmt)) << 13),
               g_qlo + (((size_t)(bh * MT + qmt)) << 13),
               (uint32_t)r * 128, nullptr);
    }
    {   // K + kk
        int nt = n >> 6, r = n & 63;
        float ss = 0.f;
        split8(k + (size_t)rown * 64 + d0,
               g_khi + (((size_t)(bh * NT + nt)) << 13),
               g_klo + (((size_t)(bh * NT + nt)) << 13),
               (uint32_t)r * 128, &ss);
        ss += __shfl_xor_sync(0xffffffffu, ss, 1);
        ss += __shfl_xor_sync(0xffffffffu, ss, 2);
        ss += __shfl_xor_sync(0xffffffffu, ss, 4);
        if (c == 0) g_kk[rown] = -0.125f * LOG2E * ss;
    }
    {   // V
        int nt = n >> 6, r = n & 63;
        split8(v + (size_t)rown * 64 + d0,
               g_vhi + (((size_t)(bh * NT + nt)) << 13),
               g_vlo + (((size_t)(bh * NT + nt)) << 13),
               (uint32_t)r * 128, nullptr);
    }
}

// =========================== main kernel ===========================
// smem: KV ring of 2 x 32KB at [0,64K). Q staged at [32K,48K) in prologue
// (inside buf1's footprint), consumed to registers, then buf1 reuses it.
// Buffers indexed by LOCAL tile parity so tile kt0 always lands in buf0.
static constexpr uint32_t S_KV  = 0;
static constexpr uint32_t S_QH  = 32768;
static constexpr uint32_t S_QL  = 40960;
static constexpr uint32_t S_KK  = 65536;    // 2 x 256B
static constexpr uint32_t SMEM_BYTES = 65536 + 512;

__constant__ int c_kt0[NSPLIT] = {0, 11, 22};
__constant__ int c_kt1[NSPLIT] = {11, 22, 32};

__global__ __launch_bounds__(128, 3)
void attn_main() {
    extern __shared__ __align__(1024) uint8_t smem[];
    const uint32_t sb = smem_u32(smem);
    const int tid = threadIdx.x, wid = tid >> 5, lane = tid & 31;
    const int mt = blockIdx.x, sp = blockIdx.y, bh = blockIdx.z;
    const int kt0 = c_kt0[sp], kt1 = c_kt1[sp];
    const int mrank = lane >> 3;
    const int l7 = lane & 7;

    // ---- prologue: Q images (staged) + KV tile kt0 (-> local buf 0) ----
    {
        const uint8_t* qh = g_qhi + (((size_t)(bh * MT + mt)) << 13);
        const uint8_t* ql = g_qlo + (((size_t)(bh * MT + mt)) << 13);
        #pragma unroll
        for (int i = 0; i < 4; i++) {
            int o = (tid + 128 * i) * 16;
            cpa16(sb + S_QH + o, qh + o);
            cpa16(sb + S_QL + o, ql + o);
        }
        const size_t t0 = ((size_t)(bh * NT + kt0)) << 13;
        #pragma unroll
        for (int i = 0; i < 4; i++) {
            int o = (tid + 128 * i) * 16;
            cpa16(sb + S_KV +          o, g_khi + t0 + o);
            cpa16(sb + S_KV +  8192 + o, g_klo + t0 + o);
            cpa16(sb + S_KV + 16384 + o, g_vhi + t0 + o);
            cpa16(sb + S_KV + 24576 + o, g_vlo + t0 + o);
        }
        if (tid < 16) cpa16(sb + S_KK + tid * 16,
                            g_kk + (size_t)bh * N_ + (size_t)kt0 * 64 + tid * 4);
        cpa_commit();
        cpa_wait0();
    }
    __syncthreads();

    // ---- Q A-fragments (persist in registers) ----
    uint32_t Qh[4][4], Ql[4][4];
    {
        int qrow = wid * 16 + ((mrank & 1) << 3) + l7;
        uint32_t rbase = (uint32_t)qrow * 128;
        uint32_t rx = (uint32_t)((qrow & 7) << 4);
        #pragma unroll
        for (int ks = 0; ks < 4; ks++) {
            uint32_t colb = (uint32_t)(ks * 32 + ((mrank >> 1) << 4));
            uint32_t a = sb + S_QH + rbase + (colb ^ rx);
            ldmx4(Qh[ks], a);
            ldmx4(Ql[ks], a + 8192);
        }
    }
    // all warps must finish reading Q before buf1 (same bytes) is overwritten
    __syncthreads();

    float O[8][4];
    #pragma unroll
    for (int i = 0; i < 8; i++)
        #pragma unroll
        for (int j = 0; j < 4; j++) O[i][j] = 0.f;
    float Lp0 = 0.f, Lp1 = 0.f;

    const int krow16 = ((mrank >> 1) << 3) + l7;
    const int vrow16 = ((mrank & 1) << 3) + l7;
    const uint32_t kcol = (uint32_t)((mrank & 1) << 4);
    const uint32_t vcol = (uint32_t)((mrank >> 1) << 4);

    #pragma unroll 1
    for (int kt = kt0; kt < kt1; kt++) {
        const int lt = kt - kt0;
        const uint32_t cb = sb + S_KV + (uint32_t)(lt & 1) * 32768;

        // prefetch tile kt+1 into the other buffer
        if (kt + 1 < kt1) {
            const size_t toff = ((size_t)(bh * NT + kt + 1)) << 13;
            const uint32_t dst = sb + S_KV + (uint32_t)((lt + 1) & 1) * 32768;
            #pragma unroll
            for (int i = 0; i < 4; i++) {
                int o = (tid + 128 * i) * 16;
                cpa16(dst +          o, g_khi + toff + o);
                cpa16(dst +  8192 + o, g_klo + toff + o);
                cpa16(dst + 16384 + o, g_vhi + toff + o);
                cpa16(dst + 24576 + o, g_vlo + toff + o);
            }
            if (tid < 16) cpa16(sb + S_KK + ((lt + 1) & 1) * 256 + tid * 16,
                                g_kk + (size_t)bh * N_ + (size_t)(kt + 1) * 64 + tid * 4);
            cpa_commit();
        }

        const float* kkp = (const float*)(smem + S_KK + (lt & 1) * 256);
        float S[8][4];
        #pragma unroll
        for (int i = 0; i < 8; i++)
            #pragma unroll
            for (int j = 0; j < 4; j++) S[i][j] = 0.f;

        // ================ S = Q . K^T (3-term split) ================
        #pragma unroll
        for (int ks = 0; ks < 4; ks++) {
            #pragma unroll
            for (int np = 0; np < 4; np++) {
                int row = np * 16 + krow16;
                uint32_t colb = (uint32_t)(ks * 32) + kcol;
                uint32_t a = cb + (uint32_t)row * 128 + (colb ^ (uint32_t)((row & 7) << 4));
                uint32_t KBh[4], KBl[4];
                ldmx4(KBh, a);
                ldmx4(KBl, a + 8192);
                mma16816(S[2 * np],     Qh[ks], KBh[0], KBh[1]);
                mma16816(S[2 * np + 1], Qh[ks], KBh[2], KBh[3]);
                mma16816(S[2 * np],     Ql[ks], KBh[0], KBh[1]);
                mma16816(S[2 * np + 1], Ql[ks], KBh[2], KBh[3]);
                mma16816(S[2 * np],     Qh[ks], KBl[0], KBl[1]);
                mma16816(S[2 * np + 1], Qh[ks], KBl[2], KBl[3]);
            }
        }

        // ================ softmax numerator -> P A-fragments ================
        uint32_t Ph[4][4], Pl[4][4];
        #pragma unroll
        for (int nt = 0; nt < 8; nt++) {
            int col = nt * 8 + 2 * (lane & 3);
            float k0 = kkp[col], k1 = kkp[col + 1];
            float p0 = ex2f(fmaf(SCALE_S, S[nt][0], k0));
            float p1 = ex2f(fmaf(SCALE_S, S[nt][1], k1));
            float p2 = ex2f(fmaf(SCALE_S, S[nt][2], k0));
            float p3 = ex2f(fmaf(SCALE_S, S[nt][3], k1));
            Lp0 += p0 + p1;
            Lp1 += p2 + p3;
            uint32_t h01 = pkbf2(p1, p0);
            uint32_t h23 = pkbf2(p3, p2);
            uint32_t l01 = pkbf2(p1 - hi_f32(h01), p0 - lo_f32(h01));
            uint32_t l23 = pkbf2(p3 - hi_f32(h23), p2 - lo_f32(h23));
            Ph[nt >> 1][(nt & 1) * 2]     = h01;
            Ph[nt >> 1][(nt & 1) * 2 + 1] = h23;
            Pl[nt >> 1][(nt & 1) * 2]     = l01;
            Pl[nt >> 1][(nt & 1) * 2 + 1] = l23;
        }

        // ================ O += P . V (3-term split) ================
        #pragma unroll
        for (int j = 0; j < 4; j++) {
            #pragma unroll
            for (int dp = 0; dp < 4; dp++) {
                int row = j * 16 + vrow16;
                uint32_t colb = (uint32_t)(dp * 32) + vcol;
                uint32_t a = cb + 16384 + (uint32_t)row * 128 + (colb ^ (uint32_t)((row & 7) << 4));
                uint32_t VBh[4], VBl[4];
                ldmx4t(VBh, a);
                ldmx4t(VBl, a + 8192);
                mma16816(O[2 * dp],     Ph[j], VBh[0], VBh[1]);
                mma16816(O[2 * dp + 1], Ph[j], VBh[2], VBh[3]);
                mma16816(O[2 * dp],     Pl[j], VBh[0], VBh[1]);
                mma16816(O[2 * dp + 1], Pl[j], VBh[2], VBh[3]);
                mma16816(O[2 * dp],     Ph[j], VBl[0], VBl[1]);
                mma16816(O[2 * dp + 1], Ph[j], VBl[2], VBl[3]);
            }
        }

        if (kt + 1 < kt1) {
            cpa_wait0();
            __syncthreads();
        }
    }

    // ---- epilogue: quad-reduce L, store UNNORMALIZED partials ----
    Lp0 += __shfl_xor_sync(0xffffffffu, Lp0, 1);
    Lp0 += __shfl_xor_sync(0xffffffffu, Lp0, 2);
    Lp1 += __shfl_xor_sync(0xffffffffu, Lp1, 1);
    Lp1 += __shfl_xor_sync(0xffffffffu, Lp1, 2);

    const int r0 = mt * BM + wid * 16 + (lane >> 2);
    const int dbase = 2 * (lane & 3);
    const size_t prow = ((size_t)(sp * BH + bh)) * N_ + r0;
    float* o0 = g_opart + (prow) * 64;
    float* o1 = g_opart + (prow + 8) * 64;
    #pragma unroll
    for (int dt = 0; dt < 8; dt++) {
        int d = dt * 8 + dbase;
        *(float2*)(o0 + d) = make_float2(O[dt][0], O[dt][1]);
        *(float2*)(o1 + d) = make_float2(O[dt][2], O[dt][3]);
    }
    if ((lane & 3) == 0) {
        g_lpart[prow] = Lp0;
        g_lpart[prow + 8] = Lp1;
    }
}

// ==================== combine: out = sum(O)/sum(L), transpose to [B,N,H,D] ====================
__global__ void combine_kernel(float* __restrict__ out) {
    int idx = blockIdx.x * 256 + threadIdx.x;   // BH*N*16 = 1,048,576
    int d  = (idx & 15) * 4;
    int n  = (idx >> 4) & (N_ - 1);
    int bh = idx >> 15;
    int b = bh >> 3, h = bh & 7;
    const size_t row = (size_t)bh * N_ + n;
    const size_t so = (size_t)BH * N_ * 64;
    const size_t sl = (size_t)BH * N_;

    float4 a0 = *(const float4*)(g_opart + row * 64 + d);
    float4 a1 = *(const float4*)(g_opart + so + row * 64 + d);
    float4 a2 = *(const float4*)(g_opart + 2 * so + row * 64 + d);
    float L = g_lpart[row] + g_lpart[sl + row] + g_lpart[2 * sl + row];
    float inv = 1.0f / L;
    float4 r;
    r.x = (a0.x + a1.x + a2.x) * inv;
    r.y = (a0.y + a1.y + a2.y) * inv;
    r.z = (a0.z + a1.z + a2.z) * inv;
    r.w = (a0.w + a1.w + a2.w) * inv;
    *(float4*)(out + (((size_t)(b * N_ + n) * H_ + h) << 6) + d) = r;
}

// ============================ launch ============================
extern "C" void kernel_launch(void* const* d_in, const int* in_sizes, int n_in,
                              void* d_out, int out_size) {
    (void)in_sizes; (void)n_in; (void)out_size;
    const float* q = (const float*)d_in[0];
    const float* k = (const float*)d_in[1];
    const float* v = (const float*)d_in[2];
    float* out = (float*)d_out;

    prep_kernel<<<BH * N_ * 8 / 256, 256>>>(q, k, v);

    cudaFuncSetAttribute(attn_main, cudaFuncAttributeMaxDynamicSharedMemorySize, SMEM_BYTES);
    dim3 grid(MT, NSPLIT, BH);
    attn_main<<<grid, 128, SMEM_BYTES>>>();

    combine_kernel<<<BH * N_ * 16 / 256, 256>>>(out);
}

// round 9
// speedup vs baseline: 1.1202x; 1.0388x over previous
#include <cuda_runtime.h>
#include <cuda_bf16.h>
#include <cstdint>

// ============================ problem dims ============================
static constexpr int B_ = 4, H_ = 8, N_ = 2048, D_ = 64;
static constexpr int BH = B_ * H_;   // 32
static constexpr int BM = 64;        // query rows per CTA
static constexpr int BN = 64;        // keys per tile
static constexpr int MT = N_ / BM;   // 32
static constexpr int NT = N_ / BN;   // 32
static constexpr int TILES_PER_RANK = NT / 2;   // 16

// ==================== pre-converted gmem scratch ======================
__device__ __align__(128) uint8_t g_qhi[(size_t)BH * MT * 8192];
__device__ __align__(128) uint8_t g_qlo[(size_t)BH * MT * 8192];
__device__ __align__(128) uint8_t g_khi[(size_t)BH * NT * 8192];
__device__ __align__(128) uint8_t g_klo[(size_t)BH * NT * 8192];
__device__ __align__(128) uint8_t g_vhi[(size_t)BH * NT * 8192];
__device__ __align__(128) uint8_t g_vlo[(size_t)BH * NT * 8192];
__device__ float g_kk[(size_t)BH * N_];   // -0.125 * log2(e) * ||k||^2

// ============================ helpers =============================
__device__ __forceinline__ uint32_t smem_u32(const void* p) {
    uint32_t a;
    asm("{ .reg .u64 t; cvta.to.shared.u64 t, %1; cvt.u32.u64 %0, t; }" : "=r"(a) : "l"(p));
    return a;
}
__device__ __forceinline__ void cpa16(uint32_t s, const void* g) {
    asm volatile("cp.async.cg.shared.global [%0], [%1], 16;" :: "r"(s), "l"(g));
}
__device__ __forceinline__ void cpa_commit() { asm volatile("cp.async.commit_group;" ::: "memory"); }
__device__ __forceinline__ void cpa_wait0()  { asm volatile("cp.async.wait_group 0;" ::: "memory"); }

__device__ __forceinline__ void ldmx4(uint32_t* r, uint32_t a) {
    asm volatile("ldmatrix.sync.aligned.m8n8.x4.shared.b16 {%0,%1,%2,%3}, [%4];"
                 : "=r"(r[0]), "=r"(r[1]), "=r"(r[2]), "=r"(r[3]) : "r"(a));
}
__device__ __forceinline__ void ldmx4t(uint32_t* r, uint32_t a) {
    asm volatile("ldmatrix.sync.aligned.m8n8.x4.trans.shared.b16 {%0,%1,%2,%3}, [%4];"
                 : "=r"(r[0]), "=r"(r[1]), "=r"(r[2]), "=r"(r[3]) : "r"(a));
}
__device__ __forceinline__ void mma16816(float* c, const uint32_t* a, uint32_t b0, uint32_t b1) {
    asm volatile("mma.sync.aligned.m16n8k16.row.col.f32.bf16.bf16.f32 "
                 "{%0,%1,%2,%3}, {%4,%5,%6,%7}, {%8,%9}, {%0,%1,%2,%3};"
                 : "+f"(c[0]), "+f"(c[1]), "+f"(c[2]), "+f"(c[3])
                 : "r"(a[0]), "r"(a[1]), "r"(a[2]), "r"(a[3]), "r"(b0), "r"(b1));
}
__device__ __forceinline__ uint32_t pkbf2(float up, float low) {
    uint32_t d;
    asm("cvt.rn.bf16x2.f32 %0, %1, %2;" : "=r"(d) : "f"(up), "f"(low));
    return d;
}
__device__ __forceinline__ float lo_f32(uint32_t p) { return __uint_as_float(p << 16); }
__device__ __forceinline__ float hi_f32(uint32_t p) { return __uint_as_float(p & 0xffff0000u); }
__device__ __forceinline__ float ex2f(float x) {
    float y;
    asm("ex2.approx.f32 %0, %1;" : "=f"(y) : "f"(x));
    return y;
}
static constexpr float LOG2E   = 1.4426950408889634f;
static constexpr float SCALE_S = 0.25f * LOG2E;

#define CLUSTER_SYNC() do { \
    asm volatile("barrier.cluster.arrive.aligned;" ::: "memory"); \
    asm volatile("barrier.cluster.wait.aligned;" ::: "memory"); \
} while (0)

// ====================== pre-pass: fp32 -> SW128 bf16 hi/lo images ======================
__global__ void prep_kernel(const float* __restrict__ q, const float* __restrict__ k,
                            const float* __restrict__ v) {
    int idx  = blockIdx.x * 256 + threadIdx.x;   // 0 .. BH*N*8-1
    int rown = idx >> 3;
    int c    = idx & 7;
    int d0   = c * 8;
    int bh = rown >> 11, n = rown & 2047;

    auto split8 = [&](const float* src, uint8_t* dh, uint8_t* dl, uint32_t rowoff, float* ss) {
        float xs[8];
        *(float4*)(xs)     = *(const float4*)(src);
        *(float4*)(xs + 4) = *(const float4*)(src + 4);
        uint32_t hp[4], lp[4];
        #pragma unroll
        for (int j = 0; j < 4; j++) {
            float x0 = xs[2 * j], x1 = xs[2 * j + 1];
            if (ss) *ss += x0 * x0 + x1 * x1;
            uint32_t hpair = pkbf2(x1, x0);
            hp[j] = hpair;
            lp[j] = pkbf2(x1 - hi_f32(hpair), x0 - lo_f32(hpair));
        }
        uint32_t x = rowoff + (uint32_t)d0 * 2;
        uint32_t off = x ^ ((x >> 3) & 0x70);
        *(uint4*)(dh + off) = make_uint4(hp[0], hp[1], hp[2], hp[3]);
        *(uint4*)(dl + off) = make_uint4(lp[0], lp[1], lp[2], lp[3]);
    };

    {   // Q
        int qmt = n >> 6, r = n & 63;
        split8(q + (size_t)rown * 64 + d0,
               g_qhi + (((size_t)(bh * MT + qmt)) << 13),
               g_qlo + (((size_t)(bh * MT + qmt)) << 13),
               (uint32_t)r * 128, nullptr);
    }
    {   // K + kk
        int nt = n >> 6, r = n & 63;
        float ss = 0.f;
        split8(k + (size_t)rown * 64 + d0,
               g_khi + (((size_t)(bh * NT + nt)) << 13),
               g_klo + (((size_t)(bh * NT + nt)) << 13),
               (uint32_t)r * 128, &ss);
        ss += __shfl_xor_sync(0xffffffffu, ss, 1);
        ss += __shfl_xor_sync(0xffffffffu, ss, 2);
        ss += __shfl_xor_sync(0xffffffffu, ss, 4);
        if (c == 0) g_kk[rown] = -0.125f * LOG2E * ss;
    }
    {   // V
        int nt = n >> 6, r = n & 63;
        split8(v + (size_t)rown * 64 + d0,
               g_vhi + (((size_t)(bh * NT + nt)) << 13),
               g_vlo + (((size_t)(bh * NT + nt)) << 13),
               (uint32_t)r * 128, nullptr);
    }
}

// =========================== main kernel ===========================
// smem: KV ring of 2 x 32KB at [0,64K). Q staged at [32K,48K) in prologue.
// After the loop, buf0 region doubles as the cluster-reduction area:
//   remote O partial at [0,16K), remote L at [16K,16K+512).
static constexpr uint32_t S_KV   = 0;
static constexpr uint32_t S_QH   = 32768;
static constexpr uint32_t S_QL   = 40960;
static constexpr uint32_t S_REDL = 16384;
static constexpr uint32_t S_KK   = 65536;    // 2 x 256B
static constexpr uint32_t SMEM_BYTES = 65536 + 512;

__global__ __launch_bounds__(128, 3) __cluster_dims__(2, 1, 1)
void attn_main(float* __restrict__ out) {
    extern __shared__ __align__(1024) uint8_t smem[];
    const uint32_t sb = smem_u32(smem);
    const int tid = threadIdx.x, wid = tid >> 5, lane = tid & 31;
    const int rank = blockIdx.x;           // cluster CTA rank (0/1)
    const int mt = blockIdx.y, bh = blockIdx.z;
    const int b = bh >> 3, h = bh & 7;
    const int kt0 = rank * TILES_PER_RANK;
    const int mrank = lane >> 3;
    const int l7 = lane & 7;

    // ---- prologue: Q images (staged) + KV tile kt0 (local buf 0) ----
    {
        const uint8_t* qh = g_qhi + (((size_t)(bh * MT + mt)) << 13);
        const uint8_t* ql = g_qlo + (((size_t)(bh * MT + mt)) << 13);
        #pragma unroll
        for (int i = 0; i < 4; i++) {
            int o = (tid + 128 * i) * 16;
            cpa16(sb + S_QH + o, qh + o);
            cpa16(sb + S_QL + o, ql + o);
        }
        const size_t t0 = ((size_t)(bh * NT + kt0)) << 13;
        #pragma unroll
        for (int i = 0; i < 4; i++) {
            int o = (tid + 128 * i) * 16;
            cpa16(sb + S_KV +          o, g_khi + t0 + o);
            cpa16(sb + S_KV +  8192 + o, g_klo + t0 + o);
            cpa16(sb + S_KV + 16384 + o, g_vhi + t0 + o);
            cpa16(sb + S_KV + 24576 + o, g_vlo + t0 + o);
        }
        if (tid < 16) cpa16(sb + S_KK + tid * 16,
                            g_kk + (size_t)bh * N_ + (size_t)kt0 * 64 + tid * 4);
        cpa_commit();
        cpa_wait0();
    }
    __syncthreads();

    // ---- Q A-fragments (persist in registers) ----
    uint32_t Qh[4][4], Ql[4][4];
    {
        int qrow = wid * 16 + ((mrank & 1) << 3) + l7;
        uint32_t rbase = (uint32_t)qrow * 128;
        uint32_t rx = (uint32_t)((qrow & 7) << 4);
        #pragma unroll
        for (int ks = 0; ks < 4; ks++) {
            uint32_t colb = (uint32_t)(ks * 32 + ((mrank >> 1) << 4));
            uint32_t a = sb + S_QH + rbase + (colb ^ rx);
            ldmx4(Qh[ks], a);
            ldmx4(Ql[ks], a + 8192);
        }
    }
    __syncthreads();   // Q consumed before buf1 overwrites its bytes

    float O[8][4];
    #pragma unroll
    for (int i = 0; i < 8; i++)
        #pragma unroll
        for (int j = 0; j < 4; j++) O[i][j] = 0.f;
    float Lp0 = 0.f, Lp1 = 0.f;

    const int krow16 = ((mrank >> 1) << 3) + l7;
    const int vrow16 = ((mrank & 1) << 3) + l7;
    const uint32_t kcol = (uint32_t)((mrank & 1) << 4);
    const uint32_t vcol = (uint32_t)((mrank >> 1) << 4);

    #pragma unroll 1
    for (int lt = 0; lt < TILES_PER_RANK; lt++) {
        const int kt = kt0 + lt;
        const uint32_t cb = sb + S_KV + (uint32_t)(lt & 1) * 32768;

        // prefetch tile kt+1 into the other buffer
        if (lt + 1 < TILES_PER_RANK) {
            const size_t toff = ((size_t)(bh * NT + kt + 1)) << 13;
            const uint32_t dst = sb + S_KV + (uint32_t)((lt + 1) & 1) * 32768;
            #pragma unroll
            for (int i = 0; i < 4; i++) {
                int o = (tid + 128 * i) * 16;
                cpa16(dst +          o, g_khi + toff + o);
                cpa16(dst +  8192 + o, g_klo + toff + o);
                cpa16(dst + 16384 + o, g_vhi + toff + o);
                cpa16(dst + 24576 + o, g_vlo + toff + o);
            }
            if (tid < 16) cpa16(sb + S_KK + ((lt + 1) & 1) * 256 + tid * 16,
                                g_kk + (size_t)bh * N_ + (size_t)(kt + 1) * 64 + tid * 4);
            cpa_commit();
        }

        const float* kkp = (const float*)(smem + S_KK + (lt & 1) * 256);
        float S[8][4];
        #pragma unroll
        for (int i = 0; i < 8; i++)
            #pragma unroll
            for (int j = 0; j < 4; j++) S[i][j] = 0.f;

        // ================ S = Q . K^T (3-term split) ================
        #pragma unroll
        for (int ks = 0; ks < 4; ks++) {
            #pragma unroll
            for (int np = 0; np < 4; np++) {
                int row = np * 16 + krow16;
                uint32_t colb = (uint32_t)(ks * 32) + kcol;
                uint32_t a = cb + (uint32_t)row * 128 + (colb ^ (uint32_t)((row & 7) << 4));
                uint32_t KBh[4], KBl[4];
                ldmx4(KBh, a);
                ldmx4(KBl, a + 8192);
                mma16816(S[2 * np],     Qh[ks], KBh[0], KBh[1]);
                mma16816(S[2 * np + 1], Qh[ks], KBh[2], KBh[3]);
                mma16816(S[2 * np],     Ql[ks], KBh[0], KBh[1]);
                mma16816(S[2 * np + 1], Ql[ks], KBh[2], KBh[3]);
                mma16816(S[2 * np],     Qh[ks], KBl[0], KBl[1]);
                mma16816(S[2 * np + 1], Qh[ks], KBl[2], KBl[3]);
            }
        }

        // ================ softmax numerator -> P A-fragments ================
        uint32_t Ph[4][4], Pl[4][4];
        #pragma unroll
        for (int nt = 0; nt < 8; nt++) {
            int col = nt * 8 + 2 * (lane & 3);
            float k0 = kkp[col], k1 = kkp[col + 1];
            float p0 = ex2f(fmaf(SCALE_S, S[nt][0], k0));
            float p1 = ex2f(fmaf(SCALE_S, S[nt][1], k1));
            float p2 = ex2f(fmaf(SCALE_S, S[nt][2], k0));
            float p3 = ex2f(fmaf(SCALE_S, S[nt][3], k1));
            Lp0 += p0 + p1;
            Lp1 += p2 + p3;
            uint32_t h01 = pkbf2(p1, p0);
            uint32_t h23 = pkbf2(p3, p2);
            uint32_t l01 = pkbf2(p1 - hi_f32(h01), p0 - lo_f32(h01));
            uint32_t l23 = pkbf2(p3 - hi_f32(h23), p2 - lo_f32(h23));
            Ph[nt >> 1][(nt & 1) * 2]     = h01;
            Ph[nt >> 1][(nt & 1) * 2 + 1] = h23;
            Pl[nt >> 1][(nt & 1) * 2]     = l01;
            Pl[nt >> 1][(nt & 1) * 2 + 1] = l23;
        }

        // ================ O += P . V (3-term split) ================
        #pragma unroll
        for (int j = 0; j < 4; j++) {
            #pragma unroll
            for (int dp = 0; dp < 4; dp++) {
                int row = j * 16 + vrow16;
                uint32_t colb = (uint32_t)(dp * 32) + vcol;
                uint32_t a = cb + 16384 + (uint32_t)row * 128 + (colb ^ (uint32_t)((row & 7) << 4));
                uint32_t VBh[4], VBl[4];
                ldmx4t(VBh, a);
                ldmx4t(VBl, a + 8192);
                mma16816(O[2 * dp],     Ph[j], VBh[0], VBh[1]);
                mma16816(O[2 * dp + 1], Ph[j], VBh[2], VBh[3]);
                mma16816(O[2 * dp],     Pl[j], VBh[0], VBh[1]);
                mma16816(O[2 * dp + 1], Pl[j], VBh[2], VBh[3]);
                mma16816(O[2 * dp],     Ph[j], VBl[0], VBl[1]);
                mma16816(O[2 * dp + 1], Ph[j], VBl[2], VBl[3]);
            }
        }

        if (lt + 1 < TILES_PER_RANK) {
            cpa_wait0();
            __syncthreads();
        }
    }

    // ---- quad-reduce L (all lanes hold the sums afterwards) ----
    Lp0 += __shfl_xor_sync(0xffffffffu, Lp0, 1);
    Lp0 += __shfl_xor_sync(0xffffffffu, Lp0, 2);
    Lp1 += __shfl_xor_sync(0xffffffffu, Lp1, 1);
    Lp1 += __shfl_xor_sync(0xffffffffu, Lp1, 2);

    const int r0l = wid * 16 + (lane >> 2);     // local row 0..63
    const int dbase = 2 * (lane & 3);

    // ---- cluster combine: rank1 pushes O,L into rank0's smem ----
    CLUSTER_SYNC();   // both ranks done -> rank0's buf0 region is free

    if (rank == 1) {
        #pragma unroll
        for (int dt = 0; dt < 8; dt++) {
            int d = dt * 8 + dbase;
            uint32_t a0 = sb + (uint32_t)((r0l * 64 + d) * 4);
            uint32_t a1 = sb + (uint32_t)(((r0l + 8) * 64 + d) * 4);
            uint32_t ra0, ra1;
            asm("mapa.shared::cluster.u32 %0, %1, 0;" : "=r"(ra0) : "r"(a0));
            asm("mapa.shared::cluster.u32 %0, %1, 0;" : "=r"(ra1) : "r"(a1));
            unsigned long long p0, p1;
            asm("mov.b64 %0, {%1,%2};" : "=l"(p0) : "f"(O[dt][0]), "f"(O[dt][1]));
            asm("mov.b64 %0, {%1,%2};" : "=l"(p1) : "f"(O[dt][2]), "f"(O[dt][3]));
            asm volatile("st.shared::cluster.b64 [%0], %1;" :: "r"(ra0), "l"(p0) : "memory");
            asm volatile("st.shared::cluster.b64 [%0], %1;" :: "r"(ra1), "l"(p1) : "memory");
        }
        if ((lane & 3) == 0) {
            uint32_t la0 = sb + S_REDL + (uint32_t)(r0l * 4);
            uint32_t la1 = sb + S_REDL + (uint32_t)((r0l + 8) * 4);
            uint32_t rl0, rl1;
            asm("mapa.shared::cluster.u32 %0, %1, 0;" : "=r"(rl0) : "r"(la0));
            asm("mapa.shared::cluster.u32 %0, %1, 0;" : "=r"(rl1) : "r"(la1));
            asm volatile("st.shared::cluster.f32 [%0], %1;" :: "r"(rl0), "f"(Lp0) : "memory");
            asm volatile("st.shared::cluster.f32 [%0], %1;" :: "r"(rl1), "f"(Lp1) : "memory");
        }
    }

    CLUSTER_SYNC();   // remote stores visible to rank0

    if (rank == 0) {
        const float* Or = (const float*)smem;
        const float* Lr = (const float*)(smem + S_REDL);
        float inv0 = 1.0f / (Lp0 + Lr[r0l]);
        float inv1 = 1.0f / (Lp1 + Lr[r0l + 8]);

        const int r0 = mt * BM + r0l;
        float* o0 = out + (((size_t)(b * N_ + r0) * H_ + h) << 6);
        float* o1 = out + (((size_t)(b * N_ + r0 + 8) * H_ + h) << 6);
        #pragma unroll
        for (int dt = 0; dt < 8; dt++) {
            int d = dt * 8 + dbase;
            float2 q0 = *(const float2*)(Or + r0l * 64 + d);
            float2 q1 = *(const float2*)(Or + (r0l + 8) * 64 + d);
            float2 a0 = make_float2((O[dt][0] + q0.x) * inv0, (O[dt][1] + q0.y) * inv0);
            float2 a1 = make_float2((O[dt][2] + q1.x) * inv1, (O[dt][3] + q1.y) * inv1);
            *(float2*)(o0 + d) = a0;
            *(float2*)(o1 + d) = a1;
        }
    }
}

// ============================ launch ============================
extern "C" void kernel_launch(void* const* d_in, const int* in_sizes, int n_in,
                              void* d_out, int out_size) {
    (void)in_sizes; (void)n_in; (void)out_size;
    const float* q = (const float*)d_in[0];
    const float* k = (const float*)d_in[1];
    const float* v = (const float*)d_in[2];
    float* out = (float*)d_out;

    prep_kernel<<<BH * N_ * 8 / 256, 256>>>(q, k, v);

    cudaFuncSetAttribute(attn_main, cudaFuncAttributeMaxDynamicSharedMemorySize, SMEM_BYTES);
    dim3 grid(2, MT, BH);   // cluster dim x = 2 (split-K ranks)
    attn_main<<<grid, 128, SMEM_BYTES>>>(out);
}